// round 2
// baseline (speedup 1.0000x reference)
#include <cuda_runtime.h>

#define SSIM_C1 1e-4f
#define SSIM_C2 9e-4f

// tile geometry
#define TW 64            // output tile width
#define TH 16            // output tile height
#define HW 74            // halo tile width  (TW + 10)
#define HH 26            // halo tile height (TH + 10)
#define SSTR 76          // vbuf row stride in floats (16B-aligned rows)
#define SP2  76          // s12 row stride in float2 units (608B, 16B-aligned)
#define NPAIR 37         // column pairs covering 74 halo columns
#define NCHUNK 4         // 4-row chunks per tile (TH/4)
#define NBLOCKS (16*16*64)

typedef unsigned long long u64;

__device__ __align__(16) float g_partial[NBLOCKS];

__device__ __forceinline__ u64 pack2(float lo, float hi) {
    u64 r;
    asm("mov.b64 %0, {%1,%2};" : "=l"(r) : "f"(lo), "f"(hi));
    return r;
}
__device__ __forceinline__ void unpack2(u64 v, float& lo, float& hi) {
    asm("mov.b64 {%0,%1}, %2;" : "=f"(lo), "=f"(hi) : "l"(v));
}
__device__ __forceinline__ u64 fma2(u64 a, u64 b, u64 c) {
    u64 d;
    asm("fma.rn.f32x2 %0, %1, %2, %3;" : "=l"(d) : "l"(a), "l"(b), "l"(c));
    return d;
}
__device__ __forceinline__ u64 mul2(u64 a, u64 b) {
    u64 d;
    asm("mul.rn.f32x2 %0, %1, %2;" : "=l"(d) : "l"(a), "l"(b));
    return d;
}

__global__ __launch_bounds__(256) void ssim_main(
    const float* __restrict__ img1,
    const float* __restrict__ img2,
    const float* __restrict__ kw)
{
    __shared__ __align__(16) float2 s12[HH * SP2];        // interleaved (x, y)
    __shared__ __align__(16) float vbuf[5 * TH * SSTR];   // 5 vertical-conv planes
    __shared__ float s_w[11];
    __shared__ float warpSums[8];

    const int tid = threadIdx.x;
    const int bx = blockIdx.x, by = blockIdx.y, bz = blockIdx.z;
    const int row0 = by * TH;
    const int col0 = bx * TW;

    // Recover 1D gaussian from 2D kernel: g[i] = row-sum (since sum(g)=1)
    if (tid < 11) {
        float s = 0.f;
        #pragma unroll
        for (int j = 0; j < 11; j++) s += kw[tid * 11 + j];
        s_w[tid] = s;
    }

    // ---- load halo tile, interleaved (zero padding outside image) ----
    const float* base1 = img1 + (size_t)bz * 1048576u;
    const float* base2 = img2 + (size_t)bz * 1048576u;
    for (int i = tid; i < HH * HW; i += 256) {
        int rr = i / HW;
        int cc = i - rr * HW;
        int gr = row0 - 5 + rr;
        int gc = col0 - 5 + cc;
        bool ok = ((unsigned)gr < 1024u) && ((unsigned)gc < 1024u);
        int gi = gr * 1024 + gc;
        float a = ok ? base1[gi] : 0.f;
        float b = ok ? base2[gi] : 0.f;
        s12[rr * SP2 + cc] = make_float2(a, b);
    }
    __syncthreads();

    // packed weights (both lanes identical)
    u64 w2[11];
    #pragma unroll
    for (int i = 0; i < 11; i++) w2[i] = pack2(s_w[i], s_w[i]);

    // ---- vertical pass: register-chunked (4 output rows / thread) ----
    // thread item = (pair p, chunk c); input halo rows 4c .. 4c+13 streamed once
    if (tid < NPAIR * NCHUNK) {
        int c = tid / NPAIR;
        int p = tid - c * NPAIR;
        u64 acc[4][5];
        #pragma unroll
        for (int j = 0; j < 4; j++)
            #pragma unroll
            for (int q = 0; q < 5; q++) acc[j][q] = 0;

        const float2* sp = &s12[(4 * c) * SP2 + 2 * p];
        #pragma unroll
        for (int k = 0; k < 14; k++) {
            float4 v = *(const float4*)(sp + k * SP2);
            u64 xa = pack2(v.x, v.z);
            u64 yb = pack2(v.y, v.w);
            u64 xx = mul2(xa, xa);
            u64 yy = mul2(yb, yb);
            u64 xy = mul2(xa, yb);
            #pragma unroll
            for (int j = 0; j < 4; j++) {
                int wi = k - j;
                if (wi >= 0 && wi <= 10) {
                    acc[j][0] = fma2(w2[wi], xa, acc[j][0]);
                    acc[j][1] = fma2(w2[wi], yb, acc[j][1]);
                    acc[j][2] = fma2(w2[wi], xx, acc[j][2]);
                    acc[j][3] = fma2(w2[wi], yy, acc[j][3]);
                    acc[j][4] = fma2(w2[wi], xy, acc[j][4]);
                }
            }
        }
        #pragma unroll
        for (int j = 0; j < 4; j++) {
            int off = (4 * c + j) * SSTR + 2 * p;
            #pragma unroll
            for (int q = 0; q < 5; q++)
                *(u64*)&vbuf[q * TH * SSTR + off] = acc[j][q];
        }
    }
    __syncthreads();

    // ---- horizontal pass + SSIM: each thread does 4 consecutive columns of one row ----
    const int hr  = tid >> 4;          // 0..15
    const int cl0 = (tid & 15) * 4;    // 0..60

    u64 res[5][2];
    #pragma unroll
    for (int q = 0; q < 5; q++) {
        const float* vp = &vbuf[q * TH * SSTR + hr * SSTR + cl0];
        float tv[14];
        float4 v0 = *(const float4*)(vp + 0);
        float4 v1 = *(const float4*)(vp + 4);
        float4 v2 = *(const float4*)(vp + 8);
        float2 v3 = *(const float2*)(vp + 12);
        tv[0]=v0.x; tv[1]=v0.y; tv[2]=v0.z; tv[3]=v0.w;
        tv[4]=v1.x; tv[5]=v1.y; tv[6]=v1.z; tv[7]=v1.w;
        tv[8]=v2.x; tv[9]=v2.y; tv[10]=v2.z; tv[11]=v2.w;
        tv[12]=v3.x; tv[13]=v3.y;
        u64 pk[13];
        #pragma unroll
        for (int j = 0; j < 13; j++) pk[j] = pack2(tv[j], tv[j + 1]);
        u64 a0 = 0, a1 = 0;
        #pragma unroll
        for (int j = 0; j < 11; j++) {
            a0 = fma2(w2[j], pk[j],     a0);
            a1 = fma2(w2[j], pk[j + 2], a1);
        }
        res[q][0] = a0;
        res[q][1] = a1;
    }

    float m1[4], m2[4], exx[4], eyy[4], exy[4];
    unpack2(res[0][0], m1[0], m1[1]);   unpack2(res[0][1], m1[2], m1[3]);
    unpack2(res[1][0], m2[0], m2[1]);   unpack2(res[1][1], m2[2], m2[3]);
    unpack2(res[2][0], exx[0], exx[1]); unpack2(res[2][1], exx[2], exx[3]);
    unpack2(res[3][0], eyy[0], eyy[1]); unpack2(res[3][1], eyy[2], eyy[3]);
    unpack2(res[4][0], exy[0], exy[1]); unpack2(res[4][1], exy[2], exy[3]);

    float ssum = 0.f;
    #pragma unroll
    for (int k = 0; k < 4; k++) {
        float a = m1[k], b = m2[k];
        float a2v = a * a, b2v = b * b, ab = a * b;
        float sx2 = exx[k] - a2v;
        float sy2 = eyy[k] - b2v;
        float sxy = exy[k] - ab;
        float num = (2.f * ab  + SSIM_C1) * (2.f * sxy + SSIM_C2);
        float den = (a2v + b2v + SSIM_C1) * (sx2 + sy2 + SSIM_C2);
        ssum += __fdividef(num, den);
    }

    // ---- block reduction (deterministic, no atomics) ----
    #pragma unroll
    for (int o = 16; o > 0; o >>= 1)
        ssum += __shfl_down_sync(0xffffffffu, ssum, o);
    const int wid = tid >> 5, lane = tid & 31;
    if (lane == 0) warpSums[wid] = ssum;
    __syncthreads();
    if (tid == 0) {
        float tot = 0.f;
        #pragma unroll
        for (int i = 0; i < 8; i++) tot += warpSums[i];
        int bid = bx + 16 * (by + 64 * bz);
        g_partial[bid] = tot;
    }
}

__global__ __launch_bounds__(1024) void ssim_finish(float* __restrict__ out)
{
    __shared__ double wsum[32];
    const int tid = threadIdx.x;
    const float4* p4 = (const float4*)g_partial;   // 4096 float4
    double s = 0.0;
    #pragma unroll
    for (int i = 0; i < 4; i++) {
        float4 v = p4[tid + i * 1024];
        s += (double)v.x + (double)v.y + (double)v.z + (double)v.w;
    }
    #pragma unroll
    for (int o = 16; o > 0; o >>= 1)
        s += __shfl_down_sync(0xffffffffu, s, o);
    if ((tid & 31) == 0) wsum[tid >> 5] = s;
    __syncthreads();
    if (tid < 32) {
        double t = wsum[tid];
        #pragma unroll
        for (int o = 16; o > 0; o >>= 1)
            t += __shfl_down_sync(0xffffffffu, t, o);
        if (tid == 0) out[0] = (float)(t / 16777216.0);
    }
}

extern "C" void kernel_launch(void* const* d_in, const int* in_sizes, int n_in,
                              void* d_out, int out_size)
{
    const float* img1 = (const float*)d_in[0];
    const float* img2 = (const float*)d_in[1];
    const float* kw   = (const float*)d_in[2];
    float* out = (float*)d_out;

    dim3 grid(16, 64, 16);   // 1024/64 x-tiles, 1024/16 y-tiles, 16 batch
    ssim_main<<<grid, 256>>>(img1, img2, kw);
    ssim_finish<<<1, 1024>>>(out);
}